// round 1
// baseline (speedup 1.0000x reference)
#include <cuda_runtime.h>
#include <cuda_bf16.h>

#define D_DIM 128
#define C_DIM 16
#define MAX_NODES 100000
#define NPB 128   // nodes per block == threads per block in precompute

// Scratch: per-node projections, layout [n][0:16]=P (src proj), [n][16:32]=Q (dst proj).
// 100k * 32 * 4B = 12.8 MB -> fits in L2 entirely.
__device__ float g_PQ[(size_t)MAX_NODES * 32];
__device__ int g_idx64;

__constant__ float c_W[16 * 256];  // raw W, row-major [C=16][2D=256]
__constant__ float c_b[16];

// ---------------------------------------------------------------------------
// Detect whether edge index arrays are int64 (odd 32-bit words all zero) or int32.
// ---------------------------------------------------------------------------
__global__ void detect_idx_kernel(const int* __restrict__ src_words) {
    int all0 = 1;
#pragma unroll
    for (int i = 1; i < 64; i += 2) all0 &= (src_words[i] == 0);
    g_idx64 = all0;
}

// ---------------------------------------------------------------------------
// Kernel 1: PQ[n][c]    = sum_d h[n][d] * W[c][d]        (c in 0..15)
//           PQ[n][16+c] = sum_d h[n][d] * W[c][128+d]
// One thread per node, 32 fp32 accumulators, h staged through shared memory
// (conflict-free via +1 padding), W read via uniform constant loads (LDCU).
// ---------------------------------------------------------------------------
__global__ __launch_bounds__(NPB) void precompute_kernel(const float* __restrict__ h,
                                                         int n_nodes) {
    __shared__ float sh[NPB][33];   // row stride 33 words -> bank-conflict-free column reads

    const int tid = threadIdx.x;
    const int n0 = blockIdx.x * NPB;
    const int lane = tid & 31;
    const int warp = tid >> 5;      // 0..3

    float acc[32];
#pragma unroll
    for (int k = 0; k < 32; k++) acc[k] = 0.f;

    for (int d0 = 0; d0 < D_DIM; d0 += 32) {
        __syncthreads();
        // Cooperative coalesced load: h[n0 .. n0+127][d0 .. d0+31]
        // Each warp loads one row (128B) per step.
#pragma unroll 8
        for (int step = 0; step < 32; step++) {
            int row = step * 4 + warp;
            int n = n0 + row;
            float v = 0.f;
            if (n < n_nodes) v = h[(size_t)n * D_DIM + d0 + lane];
            sh[row][lane] = v;
        }
        __syncthreads();

#pragma unroll 4
        for (int d = 0; d < 32; d++) {
            float hv = sh[tid][d];      // lanes hit distinct banks (stride 33)
            int dd = d0 + d;
#pragma unroll
            for (int c = 0; c < 16; c++) {
                acc[c]      = fmaf(hv, c_W[c * 256 + dd],       acc[c]);
                acc[16 + c] = fmaf(hv, c_W[c * 256 + 128 + dd], acc[16 + c]);
            }
        }
    }

    int n = n0 + tid;
    if (n < n_nodes) {
        float4* out = reinterpret_cast<float4*>(g_PQ + (size_t)n * 32);
#pragma unroll
        for (int i = 0; i < 8; i++)
            out[i] = make_float4(acc[4 * i], acc[4 * i + 1], acc[4 * i + 2], acc[4 * i + 3]);
    }
}

// ---------------------------------------------------------------------------
// Kernel 2: out[e][c] = PQ[src[e]][c] + PQ[dst[e]][16+c] + b[c]
// One thread per edge; float4 vector loads (64B granules, 64B-aligned rows),
// PQ resident in L2 from kernel 1.
// ---------------------------------------------------------------------------
__global__ __launch_bounds__(256) void gather_kernel(const void* __restrict__ src_raw,
                                                     const void* __restrict__ dst_raw,
                                                     float* __restrict__ out,
                                                     int n_edges) {
    int e = blockIdx.x * blockDim.x + threadIdx.x;
    if (e >= n_edges) return;

    long long s, d;
    if (g_idx64) {
        s = reinterpret_cast<const long long*>(src_raw)[e];
        d = reinterpret_cast<const long long*>(dst_raw)[e];
    } else {
        s = reinterpret_cast<const int*>(src_raw)[e];
        d = reinterpret_cast<const int*>(dst_raw)[e];
    }

    const float4* p = reinterpret_cast<const float4*>(g_PQ + (size_t)s * 32);
    const float4* q = reinterpret_cast<const float4*>(g_PQ + (size_t)d * 32 + 16);
    float4* o = reinterpret_cast<float4*>(out + (size_t)e * 16);
    const float4* bb = reinterpret_cast<const float4*>(c_b);

#pragma unroll
    for (int i = 0; i < 4; i++) {
        float4 a = p[i];
        float4 c = q[i];
        float4 bv = bb[i];
        o[i] = make_float4(a.x + c.x + bv.x,
                           a.y + c.y + bv.y,
                           a.z + c.z + bv.z,
                           a.w + c.w + bv.w);
    }
}

// ---------------------------------------------------------------------------
// Inputs (metadata order): h [N*128 f32], src [E idx], dst [E idx],
//                          W [16*256 f32], b [16 f32]. Output: [E*16 f32].
// ---------------------------------------------------------------------------
extern "C" void kernel_launch(void* const* d_in, const int* in_sizes, int n_in,
                              void* d_out, int out_size) {
    const float* h = (const float*)d_in[0];
    const void* src = d_in[1];
    const void* dst = d_in[2];
    const float* W = (const float*)d_in[3];
    const float* b = (const float*)d_in[4];

    int n_nodes = in_sizes[0] / D_DIM;
    int n_edges = in_sizes[1];

    cudaMemcpyToSymbolAsync(c_W, W, 16 * 256 * sizeof(float), 0,
                            cudaMemcpyDeviceToDevice, 0);
    cudaMemcpyToSymbolAsync(c_b, b, 16 * sizeof(float), 0,
                            cudaMemcpyDeviceToDevice, 0);

    detect_idx_kernel<<<1, 1>>>((const int*)src);

    int blocks1 = (n_nodes + NPB - 1) / NPB;
    precompute_kernel<<<blocks1, NPB>>>(h, n_nodes);

    int blocks2 = (n_edges + 255) / 256;
    gather_kernel<<<blocks2, 256>>>(src, dst, (float*)d_out, n_edges);
}

// round 2
// speedup vs baseline: 17.0427x; 17.0427x over previous
#include <cuda_runtime.h>
#include <cuda_bf16.h>

#define D_DIM 128
#define MAX_NODES 100000

// Per-node projections: [n][0:16] = h[n]·W_s + b (P), [n][16:32] = h[n]·W_d (Q).
// 100k * 32 * 4B = 12.8 MB -> resident in L2.
__device__ float g_PQ[(size_t)MAX_NODES * 32];
__device__ int g_idx64;

// ---------------------------------------------------------------------------
// Detect int64 vs int32 edge indices: if int64, odd 32-bit words are all zero
// (indices in [0,100000)). If int32, odd words are random node ids (P[all 32
// zero] ~ 1e-160).
// ---------------------------------------------------------------------------
__global__ void detect_idx_kernel(const int* __restrict__ src_words) {
    int ok = (src_words[threadIdx.x * 2 + 1] == 0);
    int all = __all_sync(0xffffffffu, ok);
    if (threadIdx.x == 0) g_idx64 = all;
}

// ---------------------------------------------------------------------------
// Kernel 1 (GEMM-style): PQ[128-node tile][32 cols] per block.
// 128 threads; thread t: node-group ng = t>>3 (8 nodes), col-group cg = t&7
// (4 cols). acc[8][4] in registers. W staged once in padded shared (broadcast
// LDS, no LDC), h staged in 32-wide k-tiles. FMA-pipe bound.
// Column j (0..31): j<16 -> W_s row j (+bias), j>=16 -> W_d row j-16.
// ---------------------------------------------------------------------------
__global__ __launch_bounds__(128) void precompute_kernel(const float* __restrict__ h,
                                                         const float* __restrict__ W,
                                                         const float* __restrict__ b,
                                                         int n_nodes) {
    __shared__ float sh_W[32][129];  // [col][k], row stride 129 -> conflict-free
    __shared__ float sh_h[128][33];  // [node][k], row stride 33

    const int t = threadIdx.x;
    const int n0 = blockIdx.x * 128;
    const int ng = t >> 3;   // 0..15, 8 nodes each
    const int cg = t & 7;    // 0..7, 4 cols each
    const int lane = t & 31;
    const int warp = t >> 5;

    // Stage all of W (reordered into output-column layout): 4096 floats.
#pragma unroll
    for (int i = 0; i < 32; i++) {
        int idx = i * 128 + t;
        int j = idx >> 7;          // output col 0..31
        int k = idx & 127;
        sh_W[j][k] = W[(size_t)(j & 15) * 256 + ((j >> 4) << 7) + k];
    }

    float acc[8][4];
#pragma unroll
    for (int i = 0; i < 8; i++)
#pragma unroll
        for (int j = 0; j < 4; j++) acc[i][j] = 0.f;

    for (int kt = 0; kt < 4; kt++) {
        __syncthreads();
        // Coalesced load of h[n0..n0+127][kt*32 .. +31]; each warp: 1 row / step.
#pragma unroll 8
        for (int step = 0; step < 32; step++) {
            int row = step * 4 + warp;
            int n = n0 + row;
            float v = 0.f;
            if (n < n_nodes) v = h[(size_t)n * D_DIM + kt * 32 + lane];
            sh_h[row][lane] = v;
        }
        __syncthreads();

#pragma unroll 4
        for (int k = 0; k < 32; k++) {
            float wv[4], hv[8];
#pragma unroll
            for (int j = 0; j < 4; j++) wv[j] = sh_W[cg * 4 + j][kt * 32 + k];
#pragma unroll
            for (int i = 0; i < 8; i++) hv[i] = sh_h[ng * 8 + i][k];
#pragma unroll
            for (int i = 0; i < 8; i++)
#pragma unroll
                for (int j = 0; j < 4; j++)
                    acc[i][j] = fmaf(hv[i], wv[j], acc[i][j]);
        }
    }

    // Store, folding bias into P columns (c < 16).
#pragma unroll
    for (int i = 0; i < 8; i++) {
        int n = n0 + ng * 8 + i;
        if (n < n_nodes) {
#pragma unroll
            for (int j = 0; j < 4; j++) {
                int c = cg * 4 + j;
                float v = acc[i][j];
                if (c < 16) v += b[c];
                g_PQ[(size_t)n * 32 + c] = v;
            }
        }
    }
}

// ---------------------------------------------------------------------------
// Kernel 2: out[e][c] = P[src[e]][c] + Q[dst[e]][c]   (bias prefolded)
// 4 lanes per edge: lane handles one float4 -> a warp's P-load touches 8
// cache lines (vs 32 for thread-per-edge), 64B used per line.
// ---------------------------------------------------------------------------
__global__ __launch_bounds__(256) void gather_kernel(const void* __restrict__ src_raw,
                                                     const void* __restrict__ dst_raw,
                                                     float* __restrict__ out,
                                                     int n_edges) {
    const int t = threadIdx.x;
    const long long e = (long long)blockIdx.x * 64 + (t >> 2);
    const int comp = t & 3;
    if (e >= n_edges) return;

    long long s, d;
    if (g_idx64) {
        s = reinterpret_cast<const long long*>(src_raw)[e];
        d = reinterpret_cast<const long long*>(dst_raw)[e];
    } else {
        s = reinterpret_cast<const int*>(src_raw)[e];
        d = reinterpret_cast<const int*>(dst_raw)[e];
    }

    float4 pv = *reinterpret_cast<const float4*>(g_PQ + (size_t)s * 32 + comp * 4);
    float4 qv = *reinterpret_cast<const float4*>(g_PQ + (size_t)d * 32 + 16 + comp * 4);

    reinterpret_cast<float4*>(out)[e * 4 + comp] =
        make_float4(pv.x + qv.x, pv.y + qv.y, pv.z + qv.z, pv.w + qv.w);
}

// ---------------------------------------------------------------------------
// Inputs (metadata order): h [N*128 f32], src [E idx], dst [E idx],
//                          W [16*256 f32], b [16 f32]. Output: [E*16 f32].
// ---------------------------------------------------------------------------
extern "C" void kernel_launch(void* const* d_in, const int* in_sizes, int n_in,
                              void* d_out, int out_size) {
    const float* h = (const float*)d_in[0];
    const void* src = d_in[1];
    const void* dst = d_in[2];
    const float* W = (const float*)d_in[3];
    const float* b = (const float*)d_in[4];

    int n_nodes = in_sizes[0] / D_DIM;
    int n_edges = in_sizes[1];

    detect_idx_kernel<<<1, 32>>>((const int*)src);

    int blocks1 = (n_nodes + 127) / 128;
    precompute_kernel<<<blocks1, 128>>>(h, W, b, n_nodes);

    int blocks2 = (n_edges + 63) / 64;
    gather_kernel<<<blocks2, 256>>>(src, dst, (float*)d_out, n_edges);
}

// round 3
// speedup vs baseline: 18.5422x; 1.0880x over previous
#include <cuda_runtime.h>
#include <cuda_bf16.h>

#define D_DIM 128
#define MAX_NODES 100000

// Per-node projections: [n][0:16] = h[n]·W_s + b (P), [n][16:32] = h[n]·W_d (Q).
// 100k * 32 * 4B = 12.8 MB -> resident in L2.
__device__ float g_PQ[(size_t)MAX_NODES * 32];
__device__ int g_idx64;

// ---- packed f32x2 helpers (Blackwell FFMA2 — PTX-only, ptxas won't auto-fuse) ----
__device__ __forceinline__ unsigned long long pack2(float lo, float hi) {
    unsigned long long r;
    asm("mov.b64 %0, {%1, %2};" : "=l"(r) : "f"(lo), "f"(hi));
    return r;
}
__device__ __forceinline__ void unpack2(unsigned long long v, float& lo, float& hi) {
    asm("mov.b64 {%0, %1}, %2;" : "=f"(lo), "=f"(hi) : "l"(v));
}
__device__ __forceinline__ void ffma2(unsigned long long& d, unsigned long long a,
                                      unsigned long long b) {
    asm("fma.rn.f32x2 %0, %1, %2, %0;" : "+l"(d) : "l"(a), "l"(b));
}

// ---------------------------------------------------------------------------
// Kernel 1: per-128-node tile GEMM -> PQ, plus int64/int32 index detection
// (block 0 / warp 0; indices < 100000, so int64 => odd 32-bit words all zero).
// Thread t: nodes ng*8..ng*8+7 (as 4 f32x2 pairs), cols cg*4..cg*4+3.
// sh_h transposed [k][node] so node pairs load as LDS.128; W duplicated into
// both f32x2 halves with 4 MOVs/k (alu pipe, off the critical fma pipe).
// ---------------------------------------------------------------------------
__global__ __launch_bounds__(128) void precompute_kernel(const float* __restrict__ h,
                                                         const float* __restrict__ W,
                                                         const float* __restrict__ b,
                                                         const int* __restrict__ src_words,
                                                         int n_nodes) {
    __shared__ float sh_W[128][36];   // [k][col], row 144B (16B-aligned float4 reads)
    __shared__ float sh_h[32][132];   // [k][node], row 528B (16B-aligned pair reads)

    const int t = threadIdx.x;

    if (blockIdx.x == 0 && t < 32) {
        int ok = (src_words[t * 2 + 1] == 0);
        int all = __all_sync(0xffffffffu, ok);
        if (t == 0) g_idx64 = all;
    }

    const int n0 = blockIdx.x * 128;
    const int ng = t >> 3;    // 0..15 : 8 nodes
    const int cg = t & 7;     // 0..7  : 4 cols
    const int lane = t & 31;
    const int warp = t >> 5;

    // Stage W reordered to [k][output col]: col j<16 -> W_s row j; j>=16 -> W_d row j-16.
#pragma unroll
    for (int j = 0; j < 32; j++)
        sh_W[t][j] = W[(size_t)(j & 15) * 256 + ((j >> 4) << 7) + t];

    unsigned long long acc[4][4];     // [node-pair][col], f32x2; 0ull == {0.f,0.f}
#pragma unroll
    for (int i = 0; i < 4; i++)
#pragma unroll
        for (int j = 0; j < 4; j++) acc[i][j] = 0ull;

    for (int kt = 0; kt < 4; kt++) {
        __syncthreads();
        // Coalesced global read, transposed shared write.
#pragma unroll 8
        for (int step = 0; step < 32; step++) {
            int row = step * 4 + warp;           // node within tile
            int n = n0 + row;
            float v = (n < n_nodes) ? h[(size_t)n * D_DIM + kt * 32 + lane] : 0.f;
            sh_h[lane][row] = v;
        }
        __syncthreads();

#pragma unroll 4
        for (int k = 0; k < 32; k++) {
            const ulonglong2* hp =
                reinterpret_cast<const ulonglong2*>(&sh_h[k][ng * 8]);
            ulonglong2 h01 = hp[0], h23 = hp[1];
            unsigned long long hv[4] = {h01.x, h01.y, h23.x, h23.y};

            float4 wv = *reinterpret_cast<const float4*>(&sh_W[kt * 32 + k][cg * 4]);
            unsigned long long wd[4] = {pack2(wv.x, wv.x), pack2(wv.y, wv.y),
                                        pack2(wv.z, wv.z), pack2(wv.w, wv.w)};
#pragma unroll
            for (int ip = 0; ip < 4; ip++)
#pragma unroll
                for (int j = 0; j < 4; j++)
                    ffma2(acc[ip][j], hv[ip], wd[j]);
        }
    }

    // Epilogue: unpack, fold bias into P cols (<16), float4 stores.
    const int c0 = cg * 4;
    float4 bias = make_float4(0.f, 0.f, 0.f, 0.f);
    if (c0 < 16) bias = *reinterpret_cast<const float4*>(b + c0);

#pragma unroll
    for (int ip = 0; ip < 4; ip++) {
        float lo[4], hi[4];
#pragma unroll
        for (int j = 0; j < 4; j++) unpack2(acc[ip][j], lo[j], hi[j]);

        int na = n0 + ng * 8 + ip * 2;
        if (na < n_nodes)
            *reinterpret_cast<float4*>(g_PQ + (size_t)na * 32 + c0) =
                make_float4(lo[0] + bias.x, lo[1] + bias.y, lo[2] + bias.z, lo[3] + bias.w);
        if (na + 1 < n_nodes)
            *reinterpret_cast<float4*>(g_PQ + (size_t)(na + 1) * 32 + c0) =
                make_float4(hi[0] + bias.x, hi[1] + bias.y, hi[2] + bias.z, hi[3] + bias.w);
    }
}

// ---------------------------------------------------------------------------
// Kernel 2: out[e][c] = P[src[e]][c] + Q[dst[e]][c]  (bias prefolded).
// 4 lanes/edge (float4 each). Streaming traffic (idx, out) uses evict-first
// cache policy so the 12.8 MB PQ set stays hot in L2.
// ---------------------------------------------------------------------------
__global__ __launch_bounds__(256) void gather_kernel(const void* __restrict__ src_raw,
                                                     const void* __restrict__ dst_raw,
                                                     float* __restrict__ out,
                                                     int n_edges) {
    const int t = threadIdx.x;
    const long long e = (long long)blockIdx.x * 64 + (t >> 2);
    const int comp = t & 3;
    if (e >= n_edges) return;

    long long s, d;
    if (g_idx64) {
        s = __ldcs(reinterpret_cast<const long long*>(src_raw) + e);
        d = __ldcs(reinterpret_cast<const long long*>(dst_raw) + e);
    } else {
        s = __ldcs(reinterpret_cast<const int*>(src_raw) + e);
        d = __ldcs(reinterpret_cast<const int*>(dst_raw) + e);
    }

    float4 pv = *reinterpret_cast<const float4*>(g_PQ + (size_t)s * 32 + comp * 4);
    float4 qv = *reinterpret_cast<const float4*>(g_PQ + (size_t)d * 32 + 16 + comp * 4);

    float4 r = make_float4(pv.x + qv.x, pv.y + qv.y, pv.z + qv.z, pv.w + qv.w);
    __stcs(reinterpret_cast<float4*>(out) + e * 4 + comp, r);
}

// ---------------------------------------------------------------------------
// Inputs (metadata order): h [N*128 f32], src [E idx], dst [E idx],
//                          W [16*256 f32], b [16 f32]. Output: [E*16 f32].
// ---------------------------------------------------------------------------
extern "C" void kernel_launch(void* const* d_in, const int* in_sizes, int n_in,
                              void* d_out, int out_size) {
    const float* h = (const float*)d_in[0];
    const void* src = d_in[1];
    const void* dst = d_in[2];
    const float* W = (const float*)d_in[3];
    const float* b = (const float*)d_in[4];

    int n_nodes = in_sizes[0] / D_DIM;
    int n_edges = in_sizes[1];

    int blocks1 = (n_nodes + 127) / 128;
    precompute_kernel<<<blocks1, 128>>>(h, W, b, (const int*)src, n_nodes);

    int blocks2 = (n_edges + 63) / 64;
    gather_kernel<<<blocks2, 256>>>(src, dst, (float*)d_out, n_edges);
}